// round 6
// baseline (speedup 1.0000x reference)
#include <cuda_runtime.h>
#include <math.h>
#include <float.h>

#define NN   10000
#define EE   160000
#define INN  256
#define INE  128
#define CC   64
#define HH   4
#define HCC  256

// ---------------- scratch (device globals; no allocation allowed) ----------------
__device__ float g_Pni[NN * HCC];          // node @ W_ni  (x_j source)
__device__ float g_U[NN * HCC];            // node @ (W_nj @ A0[0:256])     (dst term)
__device__ float g_V[NN * HCC];            // node @ (W_ni @ A0[512:768])   (src term)
__device__ float g_nodet[NN * CC];         // node @ W_nt + b_nt
__device__ float g_bufA[40960000];         // [E,256] ping  (EP -> f0 -> f2)
__device__ float g_bufB[40960000];         // [E,256] pong  (f1)
__device__ float g_em[EE * CC];            // Em mlp ping
__device__ float g_em2[EE * CC];           // Em mlp pong
__device__ float g_sc[EE * HH];            // scores -> exp
__device__ float g_smax[NN * HH];
__device__ float g_den[NN * HH];
__device__ float g_agg[NN * HCC];
__device__ float g_n0[NN * CC];            // node mlp ping
__device__ float g_n1[NN * CC];            // node mlp pong / xg
__device__ float g_deg[NN];
__device__ float g_Wc1[HCC * HCC];         // W_nj @ A0[0:256]
__device__ float g_Wc2[HCC * HCC];         // W_ni @ A0[512:768]
__device__ float g_Wc3[INE * HCC];         // W_eij @ A0[256:512]

// ---------------- helpers ----------------
__device__ __forceinline__ void atomicMaxF(float* addr, float val) {
    if (val >= 0.f) atomicMax((int*)addr, __float_as_int(val));
    else            atomicMin((unsigned int*)addr, __float_as_uint(val));
}

static inline int ceildiv(int a, int b) { return (a + b - 1) / b; }

// ---------------- generic tiled GEMM: C[M,Ncol] = A[M,K] @ B[K,Ncol] (+bias)(+relu) ----------------
// Requires: Ncol % 64 == 0, K % 16 == 0. A rows guarded by M.
template <bool RELU, bool HASBIAS>
__global__ void gemm64(const float* __restrict__ A, const float* __restrict__ B,
                       const float* __restrict__ bias, float* __restrict__ C,
                       int M, int Ncol, int K)
{
    __shared__ float sA[16][68];
    __shared__ float sB[16][68];
    const int tid = threadIdx.x;
    const int tx = tid & 15, ty = tid >> 4;
    const int row0 = blockIdx.y * 64;
    const int col0 = blockIdx.x * 64;

    const int lm  = tid >> 2;          // 0..63  (A row within tile)
    const int lk  = (tid & 3) * 4;     // 0,4,8,12
    const int lkb = tid >> 4;          // 0..15  (B row within tile)
    const int lcb = (tid & 15) * 4;    // 0..60

    float acc[4][4];
#pragma unroll
    for (int i = 0; i < 4; i++)
#pragma unroll
        for (int j = 0; j < 4; j++) acc[i][j] = 0.f;

    for (int k0 = 0; k0 < K; k0 += 16) {
        float4 av = make_float4(0.f, 0.f, 0.f, 0.f);
        int ar = row0 + lm;
        if (ar < M) av = *reinterpret_cast<const float4*>(A + (size_t)ar * K + k0 + lk);
        sA[lk + 0][lm] = av.x; sA[lk + 1][lm] = av.y;
        sA[lk + 2][lm] = av.z; sA[lk + 3][lm] = av.w;

        float4 bv = *reinterpret_cast<const float4*>(B + (size_t)(k0 + lkb) * Ncol + col0 + lcb);
        sB[lkb][lcb + 0] = bv.x; sB[lkb][lcb + 1] = bv.y;
        sB[lkb][lcb + 2] = bv.z; sB[lkb][lcb + 3] = bv.w;
        __syncthreads();

#pragma unroll
        for (int k = 0; k < 16; k++) {
            float a[4], b[4];
#pragma unroll
            for (int i = 0; i < 4; i++) a[i] = sA[k][ty + 16 * i];
#pragma unroll
            for (int j = 0; j < 4; j++) b[j] = sB[k][tx + 16 * j];
#pragma unroll
            for (int i = 0; i < 4; i++)
#pragma unroll
                for (int j = 0; j < 4; j++) acc[i][j] = fmaf(a[i], b[j], acc[i][j]);
        }
        __syncthreads();
    }

#pragma unroll
    for (int i = 0; i < 4; i++) {
        int r = row0 + ty + 16 * i;
        if (r >= M) continue;
#pragma unroll
        for (int j = 0; j < 4; j++) {
            int c = col0 + tx + 16 * j;
            float v = acc[i][j];
            if (HASBIAS) v += bias[c];
            if (RELU) v = fmaxf(v, 0.f);
            C[(size_t)r * Ncol + c] = v;
        }
    }
}

// ---------------- specialized kernels ----------------
__global__ void k_init(float* __restrict__ smax, float* __restrict__ den,
                       float* __restrict__ agg, float* __restrict__ deg)
{
    int i = blockIdx.x * 256 + threadIdx.x;
    if (i < NN * HCC) agg[i] = 0.f;
    if (i < NN * HH) { smax[i] = -FLT_MAX; den[i] = 0.f; }
    if (i < NN) deg[i] = 1.f;   // self loop contributes 1 to deg[row=n]
}

// f0 = relu(EP + U[dst] + V[src])  (in place on buf; EP already has +A0_b)
__global__ void k_combine(const int* __restrict__ src, const int* __restrict__ dst,
                          const float* __restrict__ U, const float* __restrict__ V,
                          float* __restrict__ buf)
{
    int idx = blockIdx.x * 256 + threadIdx.x;   // over E*64 float4 units
    if (idx >= EE * 64) return;
    int e = idx >> 6, q = idx & 63;
    int s = src[e], d = dst[e];
    float4 a = reinterpret_cast<float4*>(buf)[idx];
    float4 u = reinterpret_cast<const float4*>(U + (size_t)d * HCC)[q];
    float4 v = reinterpret_cast<const float4*>(V + (size_t)s * HCC)[q];
    a.x = fmaxf(a.x + u.x + v.x, 0.f);
    a.y = fmaxf(a.y + u.y + v.y, 0.f);
    a.z = fmaxf(a.z + u.z + v.z, 0.f);
    a.w = fmaxf(a.w + u.w + v.w, 0.f);
    reinterpret_cast<float4*>(buf)[idx] = a;
}

// scores[e,h] = sum_c f[e, h*64+c] * attn_flat[h*64+c]; atomicMax into smax[dst]
__global__ void k_scores(const float* __restrict__ f, const float* __restrict__ attn,
                         const int* __restrict__ dst, float* __restrict__ sc,
                         float* __restrict__ smax)
{
    int warp = (blockIdx.x * blockDim.x + threadIdx.x) >> 5;
    int lane = threadIdx.x & 31;
    if (warp >= EE) return;
    const float* fr = f + (size_t)warp * HCC;
    int c0 = lane * 8;
    float p = 0.f;
#pragma unroll
    for (int i = 0; i < 8; i++) p = fmaf(fr[c0 + i], attn[c0 + i], p);
    p += __shfl_down_sync(0xffffffffu, p, 4, 8);
    p += __shfl_down_sync(0xffffffffu, p, 2, 8);
    p += __shfl_down_sync(0xffffffffu, p, 1, 8);
    if ((lane & 7) == 0) {
        int h = lane >> 3;
        sc[warp * 4 + h] = p;
        atomicMaxF(&smax[dst[warp] * 4 + h], p);
    }
}

__global__ void k_expsum(const int* __restrict__ dst, const float* __restrict__ smax,
                         float* __restrict__ sc, float* __restrict__ den)
{
    int idx = blockIdx.x * 256 + threadIdx.x;
    if (idx >= EE * HH) return;
    int e = idx >> 2, h = idx & 3;
    int d = dst[e];
    float ex = expf(sc[idx] - smax[d * 4 + h]);
    sc[idx] = ex;
    atomicAdd(&den[d * 4 + h], ex);
}

// alpha = ex/den[dst]; attn_w = alpha . lin; agg[dst] += Pni[src] * alpha (per head)
__global__ void k_alpha(const int* __restrict__ src, const int* __restrict__ dst,
                        const float* __restrict__ sc, const float* __restrict__ den,
                        const float* __restrict__ lin, const float* __restrict__ Pni,
                        float* __restrict__ agg, float* __restrict__ attnw)
{
    int gid = blockIdx.x * 256 + threadIdx.x;
    int e = gid >> 6, t = gid & 63;
    if (e >= EE) return;
    int s = src[e], d = dst[e];
    int h = t >> 4;
    float alpha = sc[e * 4 + h] / den[d * 4 + h];
    if (t == 0) {
        float aw = 0.f;
#pragma unroll
        for (int hh = 0; hh < 4; hh++) aw = fmaf(sc[e * 4 + hh] / den[d * 4 + hh], lin[hh], aw);
        attnw[e] = aw;
    }
    float4 pv = reinterpret_cast<const float4*>(Pni + (size_t)s * HCC)[t];
    float* ag = agg + (size_t)d * HCC + t * 4;
    atomicAdd(ag + 0, pv.x * alpha);
    atomicAdd(ag + 1, pv.y * alpha);
    atomicAdd(ag + 2, pv.z * alpha);
    atomicAdd(ag + 3, pv.w * alpha);
}

__global__ void k_addinto(float* __restrict__ out, const float* __restrict__ a, int n)
{
    int i = blockIdx.x * 256 + threadIdx.x;
    if (i < n) out[i] += a[i];
}

__global__ void k_deg(const int* __restrict__ src, const int* __restrict__ dst,
                      float* __restrict__ deg)
{
    int e = blockIdx.x * 256 + threadIdx.x;
    if (e >= EE) return;
    int s = src[e];
    if (s != dst[e]) atomicAdd(&deg[s], 1.f);
}

__global__ void k_dinv(float* __restrict__ deg)
{
    int i = blockIdx.x * 256 + threadIdx.x;
    if (i < NN) deg[i] = rsqrtf(deg[i]);   // deg >= 1 always
}

__global__ void k_gcn_self(const float* __restrict__ dinv, const float* __restrict__ xg,
                           const float* __restrict__ gb, float* __restrict__ outn)
{
    int idx = blockIdx.x * 256 + threadIdx.x;
    if (idx >= NN * CC) return;
    int n = idx >> 6, c = idx & 63;
    outn[idx] = dinv[n] * dinv[n] * xg[idx] + gb[c];
}

__global__ void k_gcn_scatter(const int* __restrict__ src, const int* __restrict__ dst,
                              const float* __restrict__ dinv, const float* __restrict__ xg,
                              float* __restrict__ outn)
{
    int gid = blockIdx.x * 256 + threadIdx.x;
    int e = gid >> 6, t = gid & 63;
    if (e >= EE) return;
    int s = src[e], d = dst[e];
    if (s == d) return;
    float coef = dinv[s] * dinv[d];
    atomicAdd(&outn[(size_t)d * CC + t], coef * xg[(size_t)s * CC + t]);
}

// ---------------- launch ----------------
extern "C" void kernel_launch(void* const* d_in, const int* in_sizes, int n_in,
                              void* d_out, int out_size)
{
    const float* node = (const float*)d_in[0];
    const float* ef   = (const float*)d_in[1];
    const int*   ei   = (const int*)d_in[2];
    const int* src = ei;
    const int* dst = ei + EE;
    const float* W_ni = (const float*)d_in[3];
    const float* W_nj = (const float*)d_in[4];
    const float* W_eij= (const float*)d_in[5];
    const float* W_nt = (const float*)d_in[6];
    const float* b_nt = (const float*)d_in[7];
    const float* W_et = (const float*)d_in[8];
    const float* b_et = (const float*)d_in[9];
    const float* A0W  = (const float*)d_in[10];
    const float* A0b  = (const float*)d_in[11];
    const float* A1W  = (const float*)d_in[12];
    const float* A1b  = (const float*)d_in[13];
    const float* A2W  = (const float*)d_in[14];
    const float* A2b  = (const float*)d_in[15];
    const float* attn = (const float*)d_in[16];
    const float* Nm0W = (const float*)d_in[17];
    const float* Nm0b = (const float*)d_in[18];
    const float* Nm1W = (const float*)d_in[19];
    const float* Nm1b = (const float*)d_in[20];
    const float* Nm2W = (const float*)d_in[21];
    const float* Nm2b = (const float*)d_in[22];
    const float* Em0W = (const float*)d_in[23];
    const float* Em0b = (const float*)d_in[24];
    const float* Em1W = (const float*)d_in[25];
    const float* Em1b = (const float*)d_in[26];
    const float* Em2W = (const float*)d_in[27];
    const float* Em2b = (const float*)d_in[28];
    const float* linW = (const float*)d_in[29];
    const float* gcnW = (const float*)d_in[30];
    const float* gcnb = (const float*)d_in[31];

    float *Pni, *U, *V, *nodet, *bufA, *bufB, *em, *em2, *sc, *smax, *den, *agg;
    float *n0, *n1, *deg, *Wc1, *Wc2, *Wc3;
    cudaGetSymbolAddress((void**)&Pni,  g_Pni);
    cudaGetSymbolAddress((void**)&U,    g_U);
    cudaGetSymbolAddress((void**)&V,    g_V);
    cudaGetSymbolAddress((void**)&nodet,g_nodet);
    cudaGetSymbolAddress((void**)&bufA, g_bufA);
    cudaGetSymbolAddress((void**)&bufB, g_bufB);
    cudaGetSymbolAddress((void**)&em,   g_em);
    cudaGetSymbolAddress((void**)&em2,  g_em2);
    cudaGetSymbolAddress((void**)&sc,   g_sc);
    cudaGetSymbolAddress((void**)&smax, g_smax);
    cudaGetSymbolAddress((void**)&den,  g_den);
    cudaGetSymbolAddress((void**)&agg,  g_agg);
    cudaGetSymbolAddress((void**)&n0,   g_n0);
    cudaGetSymbolAddress((void**)&n1,   g_n1);
    cudaGetSymbolAddress((void**)&deg,  g_deg);
    cudaGetSymbolAddress((void**)&Wc1,  g_Wc1);
    cudaGetSymbolAddress((void**)&Wc2,  g_Wc2);
    cudaGetSymbolAddress((void**)&Wc3,  g_Wc3);

    float* out_node = (float*)d_out;               // [N,64]
    float* out_edge = out_node + NN * CC;          // [E,64]
    float* out_attn = out_edge + (size_t)EE * CC;  // [E]

    auto gemm = [&](const float* A, const float* B, const float* bias, float* C,
                    int M, int Ncol, int K, bool relu) {
        dim3 grid(Ncol / 64, ceildiv(M, 64));
        if (bias) {
            if (relu) gemm64<true,  true ><<<grid, 256>>>(A, B, bias, C, M, Ncol, K);
            else      gemm64<false, true ><<<grid, 256>>>(A, B, bias, C, M, Ncol, K);
        } else {
            if (relu) gemm64<true,  false><<<grid, 256>>>(A, B, bias, C, M, Ncol, K);
            else      gemm64<false, false><<<grid, 256>>>(A, B, bias, C, M, Ncol, K);
        }
    };

    // 0) init accumulators
    k_init<<<ceildiv(NN * HCC, 256), 256>>>(smax, den, agg, deg);

    // 1) weight pre-combination (tiny GEMMs)
    gemm(W_nj,  A0W,             nullptr, Wc1, HCC, HCC, HCC, false);   // dst block
    gemm(W_ni,  A0W + 512 * HCC, nullptr, Wc2, HCC, HCC, HCC, false);   // src block
    gemm(W_eij, A0W + 256 * HCC, nullptr, Wc3, INE, HCC, HCC, false);   // edge block

    // 2) node-level projections
    gemm(node, W_ni, nullptr, Pni,   NN, HCC, INN, false);
    gemm(node, Wc1,  nullptr, U,     NN, HCC, INN, false);
    gemm(node, Wc2,  nullptr, V,     NN, HCC, INN, false);
    gemm(node, W_nt, b_nt,    nodet, NN, CC,  INN, false);

    // 3) edge-level projections
    gemm(ef, Wc3,  A0b,  bufA,     EE, HCC, INE, false);   // EP + A0_b
    gemm(ef, W_et, b_et, out_edge, EE, CC,  INE, false);   // edge_t directly into output

    // 4) f = relu-MLP chain over edges
    k_combine<<<ceildiv(EE * 64, 256), 256>>>(src, dst, U, V, bufA);   // f0
    gemm(bufA, A1W, A1b, bufB, EE, HCC, HCC, true);                    // f1
    gemm(bufB, A2W, A2b, bufA, EE, HCC, HCC, true);                    // f2 == f (leaky is identity on relu output)

    // 5) attention softmax over dst segments
    k_scores<<<ceildiv(EE * 32, 256), 256>>>(bufA, attn, dst, sc, smax);
    k_expsum<<<ceildiv(EE * HH, 256), 256>>>(dst, smax, sc, den);
    k_alpha <<<ceildiv(EE * 64, 256), 256>>>(src, dst, sc, den, linW, Pni, agg, out_attn);

    // 6) edge output MLP: edge_out = edge_t + mlp3(f)
    gemm(bufA, Em0W, Em0b, em,  EE, CC, HCC, true);
    gemm(em,   Em1W, Em1b, em2, EE, CC, CC,  true);
    gemm(em2,  Em2W, Em2b, em,  EE, CC, CC,  true);
    k_addinto<<<ceildiv(EE * CC, 256), 256>>>(out_edge, em, EE * CC);

    // 7) node output MLP + residual, then GCN transform
    gemm(agg, Nm0W, Nm0b, n0, NN, CC, HCC, true);
    gemm(n0,  Nm1W, Nm1b, n1, NN, CC, CC,  true);
    gemm(n1,  Nm2W, Nm2b, n0, NN, CC, CC,  true);
    k_addinto<<<ceildiv(NN * CC, 256), 256>>>(n0, nodet, NN * CC);     // node_out
    gemm(n0, gcnW, nullptr, n1, NN, CC, CC, false);                    // xg

    // 8) GCN normalize + aggregate
    k_deg<<<ceildiv(EE, 256), 256>>>(src, dst, deg);
    k_dinv<<<ceildiv(NN, 256), 256>>>(deg);
    k_gcn_self<<<ceildiv(NN * CC, 256), 256>>>(deg, n1, gcnb, out_node);
    k_gcn_scatter<<<ceildiv(EE * 64, 256), 256>>>(src, dst, deg, n1, out_node);
}

// round 9
// speedup vs baseline: 1.2608x; 1.2608x over previous
#include <cuda_runtime.h>
#include <math.h>
#include <float.h>

#define NN   10000
#define EE   160000
#define INN  256
#define INE  128
#define CC   64
#define HH   4
#define HCC  256

// ---------------- scratch (device globals; no allocation allowed) ----------------
__device__ __align__(16) float g_Pni[NN * HCC];
__device__ __align__(16) float g_U[NN * HCC];
__device__ __align__(16) float g_V[NN * HCC];
__device__ __align__(16) float g_nodet[NN * CC];
__device__ __align__(16) float g_bufA[(size_t)EE * HCC];
__device__ __align__(16) float g_bufB[(size_t)EE * HCC];
__device__ __align__(16) float g_em[EE * CC];
__device__ __align__(16) float g_em2[EE * CC];
__device__ __align__(16) float g_sc[EE * HH];
__device__ __align__(16) float g_smax[NN * HH];
__device__ __align__(16) float g_den[NN * HH];
__device__ __align__(16) float g_agg[NN * HCC];
__device__ __align__(16) float g_n0[NN * CC];
__device__ __align__(16) float g_n1[NN * CC];
__device__ __align__(16) float g_deg[NN];
__device__ __align__(16) float g_Wc1[HCC * HCC];
__device__ __align__(16) float g_Wc2[HCC * HCC];
__device__ __align__(16) float g_Wc3[INE * HCC];

// ---------------- helpers ----------------
__device__ __forceinline__ void atomicMaxF(float* addr, float val) {
    if (val >= 0.f) atomicMax((int*)addr, __float_as_int(val));
    else            atomicMin((unsigned int*)addr, __float_as_uint(val));
}

static inline int ceildiv(int a, int b) { return (a + b - 1) / b; }

// =====================================================================
// GEMM 128x128 tile, 256 threads, 8x8 per thread, double-buffered smem.
// Requires Ncol % 128 == 0, K % 16 == 0. A rows guarded by M.
// Epilogue options: bias, COMBINE (+U[dst]+V[src], for EGAT f0), relu, +Cadd.
// =====================================================================
template <bool RELU, bool HASBIAS, bool COMBINE, bool ADDC>
__global__ __launch_bounds__(256, 2)
void gemm128(const float* __restrict__ A, const float* __restrict__ B,
             const float* __restrict__ bias, float* __restrict__ C,
             int M, int Ncol, int K,
             const int* __restrict__ srcI, const int* __restrict__ dstI,
             const float* __restrict__ U, const float* __restrict__ V,
             const float* __restrict__ Cadd)
{
    __shared__ float sA[2][16][132];
    __shared__ float sB[2][16][132];
    const int tid = threadIdx.x;
    const int ty = tid >> 4, tx = tid & 15;
    const int row0 = blockIdx.y * 128, col0 = blockIdx.x * 128;

    float acc[8][8];
#pragma unroll
    for (int i = 0; i < 8; i++)
#pragma unroll
        for (int j = 0; j < 8; j++) acc[i][j] = 0.f;

    const int nk = K >> 4;

    auto load_tile = [&](int t, int st) {
        const int k0 = t << 4;
#pragma unroll
        for (int i = 0; i < 2; i++) {
            int idx = tid + i * 256;
            int r = idx >> 2, kq = (idx & 3) << 2;
            float4 v = make_float4(0.f, 0.f, 0.f, 0.f);
            if (row0 + r < M)
                v = *reinterpret_cast<const float4*>(A + (size_t)(row0 + r) * K + k0 + kq);
            sA[st][kq + 0][r] = v.x; sA[st][kq + 1][r] = v.y;
            sA[st][kq + 2][r] = v.z; sA[st][kq + 3][r] = v.w;
        }
#pragma unroll
        for (int i = 0; i < 2; i++) {
            int idx = tid + i * 256;
            int br = idx >> 5, bq = (idx & 31) << 2;
            float4 v = *reinterpret_cast<const float4*>(B + (size_t)(k0 + br) * Ncol + col0 + bq);
            *reinterpret_cast<float4*>(&sB[st][br][bq]) = v;
        }
    };

    load_tile(0, 0);
    __syncthreads();

    for (int t = 0; t < nk; t++) {
        const int cur = t & 1;
        if (t + 1 < nk) load_tile(t + 1, cur ^ 1);
#pragma unroll
        for (int k = 0; k < 16; k++) {
            float a[8], b[8];
            *reinterpret_cast<float4*>(a)     = *reinterpret_cast<const float4*>(&sA[cur][k][ty * 8]);
            *reinterpret_cast<float4*>(a + 4) = *reinterpret_cast<const float4*>(&sA[cur][k][ty * 8 + 4]);
            *reinterpret_cast<float4*>(b)     = *reinterpret_cast<const float4*>(&sB[cur][k][tx * 8]);
            *reinterpret_cast<float4*>(b + 4) = *reinterpret_cast<const float4*>(&sB[cur][k][tx * 8 + 4]);
#pragma unroll
            for (int i = 0; i < 8; i++)
#pragma unroll
                for (int j = 0; j < 8; j++)
                    acc[i][j] = fmaf(a[i], b[j], acc[i][j]);
        }
        __syncthreads();
    }

#pragma unroll
    for (int i = 0; i < 8; i++) {
        const int r = row0 + ty * 8 + i;
        if (r >= M) continue;
        int s = 0, d = 0;
        if (COMBINE) { s = srcI[r]; d = dstI[r]; }
#pragma unroll
        for (int j0 = 0; j0 < 8; j0 += 4) {
            const int c = col0 + tx * 8 + j0;
            float4 v = make_float4(acc[i][j0], acc[i][j0 + 1], acc[i][j0 + 2], acc[i][j0 + 3]);
            if (HASBIAS) {
                v.x += bias[c + 0]; v.y += bias[c + 1];
                v.z += bias[c + 2]; v.w += bias[c + 3];
            }
            if (COMBINE) {
                float4 u = *reinterpret_cast<const float4*>(U + (size_t)d * HCC + c);
                float4 w = *reinterpret_cast<const float4*>(V + (size_t)s * HCC + c);
                v.x += u.x + w.x; v.y += u.y + w.y;
                v.z += u.z + w.z; v.w += u.w + w.w;
            }
            if (RELU) {
                v.x = fmaxf(v.x, 0.f); v.y = fmaxf(v.y, 0.f);
                v.z = fmaxf(v.z, 0.f); v.w = fmaxf(v.w, 0.f);
            }
            if (ADDC) {
                float4 ad = *reinterpret_cast<const float4*>(Cadd + (size_t)r * Ncol + c);
                v.x += ad.x; v.y += ad.y; v.z += ad.z; v.w += ad.w;
            }
            *reinterpret_cast<float4*>(C + (size_t)r * Ncol + c) = v;
        }
    }
}

// =====================================================================
// GEMM 128x64 tile, 128 threads, 8x8 per thread, double-buffered.
// Ncol fixed = 64. Requires K % 16 == 0.
// =====================================================================
template <bool RELU, bool HASBIAS, bool ADDC>
__global__ __launch_bounds__(128, 4)
void gemmN64(const float* __restrict__ A, const float* __restrict__ B,
             const float* __restrict__ bias, float* __restrict__ C,
             int M, int K, const float* __restrict__ Cadd)
{
    __shared__ float sA[2][16][132];
    __shared__ float sB[2][16][68];
    const int tid = threadIdx.x;
    const int ty = tid >> 3, tx = tid & 7;
    const int row0 = blockIdx.x * 128;

    float acc[8][8];
#pragma unroll
    for (int i = 0; i < 8; i++)
#pragma unroll
        for (int j = 0; j < 8; j++) acc[i][j] = 0.f;

    const int nk = K >> 4;

    auto load_tile = [&](int t, int st) {
        const int k0 = t << 4;
#pragma unroll
        for (int i = 0; i < 4; i++) {
            int idx = tid + i * 128;
            int r = idx >> 2, kq = (idx & 3) << 2;
            float4 v = make_float4(0.f, 0.f, 0.f, 0.f);
            if (row0 + r < M)
                v = *reinterpret_cast<const float4*>(A + (size_t)(row0 + r) * K + k0 + kq);
            sA[st][kq + 0][r] = v.x; sA[st][kq + 1][r] = v.y;
            sA[st][kq + 2][r] = v.z; sA[st][kq + 3][r] = v.w;
        }
#pragma unroll
        for (int i = 0; i < 2; i++) {
            int idx = tid + i * 128;
            int br = idx >> 4, bq = (idx & 15) << 2;
            float4 v = *reinterpret_cast<const float4*>(B + (size_t)(k0 + br) * CC + bq);
            *reinterpret_cast<float4*>(&sB[st][br][bq]) = v;
        }
    };

    load_tile(0, 0);
    __syncthreads();

    for (int t = 0; t < nk; t++) {
        const int cur = t & 1;
        if (t + 1 < nk) load_tile(t + 1, cur ^ 1);
#pragma unroll
        for (int k = 0; k < 16; k++) {
            float a[8], b[8];
            *reinterpret_cast<float4*>(a)     = *reinterpret_cast<const float4*>(&sA[cur][k][ty * 8]);
            *reinterpret_cast<float4*>(a + 4) = *reinterpret_cast<const float4*>(&sA[cur][k][ty * 8 + 4]);
            *reinterpret_cast<float4*>(b)     = *reinterpret_cast<const float4*>(&sB[cur][k][tx * 8]);
            *reinterpret_cast<float4*>(b + 4) = *reinterpret_cast<const float4*>(&sB[cur][k][tx * 8 + 4]);
#pragma unroll
            for (int i = 0; i < 8; i++)
#pragma unroll
                for (int j = 0; j < 8; j++)
                    acc[i][j] = fmaf(a[i], b[j], acc[i][j]);
        }
        __syncthreads();
    }

#pragma unroll
    for (int i = 0; i < 8; i++) {
        const int r = row0 + ty * 8 + i;
        if (r >= M) continue;
#pragma unroll
        for (int j0 = 0; j0 < 8; j0 += 4) {
            const int c = tx * 8 + j0;
            float4 v = make_float4(acc[i][j0], acc[i][j0 + 1], acc[i][j0 + 2], acc[i][j0 + 3]);
            if (HASBIAS) {
                v.x += bias[c + 0]; v.y += bias[c + 1];
                v.z += bias[c + 2]; v.w += bias[c + 3];
            }
            if (RELU) {
                v.x = fmaxf(v.x, 0.f); v.y = fmaxf(v.y, 0.f);
                v.z = fmaxf(v.z, 0.f); v.w = fmaxf(v.w, 0.f);
            }
            if (ADDC) {
                float4 ad = *reinterpret_cast<const float4*>(Cadd + (size_t)r * CC + c);
                v.x += ad.x; v.y += ad.y; v.z += ad.z; v.w += ad.w;
            }
            *reinterpret_cast<float4*>(C + (size_t)r * CC + c) = v;
        }
    }
}

// ---------------- specialized kernels ----------------
__global__ void k_init(float* __restrict__ smax, float* __restrict__ den,
                       float* __restrict__ agg, float* __restrict__ deg)
{
    int i = blockIdx.x * 256 + threadIdx.x;
    if (i < NN * HCC) agg[i] = 0.f;
    if (i < NN * HH) { smax[i] = -FLT_MAX; den[i] = 0.f; }
    if (i < NN) deg[i] = 1.f;
}

__global__ void k_scores(const float* __restrict__ f, const float* __restrict__ attn,
                         const int* __restrict__ dst, float* __restrict__ sc,
                         float* __restrict__ smax)
{
    int warp = (blockIdx.x * blockDim.x + threadIdx.x) >> 5;
    int lane = threadIdx.x & 31;
    if (warp >= EE) return;
    const float* fr = f + (size_t)warp * HCC;
    int c0 = lane * 8;
    float p = 0.f;
#pragma unroll
    for (int i = 0; i < 8; i++) p = fmaf(fr[c0 + i], attn[c0 + i], p);
    p += __shfl_down_sync(0xffffffffu, p, 4, 8);
    p += __shfl_down_sync(0xffffffffu, p, 2, 8);
    p += __shfl_down_sync(0xffffffffu, p, 1, 8);
    if ((lane & 7) == 0) {
        int h = lane >> 3;
        sc[warp * 4 + h] = p;
        atomicMaxF(&smax[dst[warp] * 4 + h], p);
    }
}

__global__ void k_expsum(const int* __restrict__ dst, const float* __restrict__ smax,
                         float* __restrict__ sc, float* __restrict__ den)
{
    int idx = blockIdx.x * 256 + threadIdx.x;
    if (idx >= EE * HH) return;
    int e = idx >> 2, h = idx & 3;
    int d = dst[e];
    float ex = expf(sc[idx] - smax[d * 4 + h]);
    sc[idx] = ex;
    atomicAdd(&den[d * 4 + h], ex);
}

__global__ void k_alpha(const int* __restrict__ src, const int* __restrict__ dst,
                        const float* __restrict__ sc, const float* __restrict__ den,
                        const float* __restrict__ lin, const float* __restrict__ Pni,
                        float* __restrict__ agg, float* __restrict__ attnw)
{
    int gid = blockIdx.x * 256 + threadIdx.x;
    int e = gid >> 6, t = gid & 63;
    if (e >= EE) return;
    int s = src[e], d = dst[e];
    int h = t >> 4;
    float alpha = sc[e * 4 + h] / den[d * 4 + h];
    if (t == 0) {
        float aw = 0.f;
#pragma unroll
        for (int hh = 0; hh < 4; hh++) aw = fmaf(sc[e * 4 + hh] / den[d * 4 + hh], lin[hh], aw);
        attnw[e] = aw;
    }
    float4 pv = reinterpret_cast<const float4*>(Pni + (size_t)s * HCC)[t];
    float* ag = agg + (size_t)d * HCC + t * 4;
    atomicAdd(ag + 0, pv.x * alpha);
    atomicAdd(ag + 1, pv.y * alpha);
    atomicAdd(ag + 2, pv.z * alpha);
    atomicAdd(ag + 3, pv.w * alpha);
}

__global__ void k_deg(const int* __restrict__ src, const int* __restrict__ dst,
                      float* __restrict__ deg)
{
    int e = blockIdx.x * 256 + threadIdx.x;
    if (e >= EE) return;
    int s = src[e];
    if (s != dst[e]) atomicAdd(&deg[s], 1.f);
}

__global__ void k_dinv(float* __restrict__ deg)
{
    int i = blockIdx.x * 256 + threadIdx.x;
    if (i < NN) deg[i] = rsqrtf(deg[i]);
}

__global__ void k_gcn_self(const float* __restrict__ dinv, const float* __restrict__ xg,
                           const float* __restrict__ gb, float* __restrict__ outn)
{
    int idx = blockIdx.x * 256 + threadIdx.x;
    if (idx >= NN * CC) return;
    int n = idx >> 6, c = idx & 63;
    outn[idx] = dinv[n] * dinv[n] * xg[idx] + gb[c];
}

__global__ void k_gcn_scatter(const int* __restrict__ src, const int* __restrict__ dst,
                              const float* __restrict__ dinv, const float* __restrict__ xg,
                              float* __restrict__ outn)
{
    int gid = blockIdx.x * 256 + threadIdx.x;
    int e = gid >> 6, t = gid & 63;
    if (e >= EE) return;
    int s = src[e], d = dst[e];
    if (s == d) return;
    float coef = dinv[s] * dinv[d];
    atomicAdd(&outn[(size_t)d * CC + t], coef * xg[(size_t)s * CC + t]);
}

// ---------------- launch ----------------
extern "C" void kernel_launch(void* const* d_in, const int* in_sizes, int n_in,
                              void* d_out, int out_size)
{
    const float* node = (const float*)d_in[0];
    const float* ef   = (const float*)d_in[1];
    const int*   ei   = (const int*)d_in[2];
    const int* src = ei;
    const int* dst = ei + EE;
    const float* W_ni = (const float*)d_in[3];
    const float* W_nj = (const float*)d_in[4];
    const float* W_eij= (const float*)d_in[5];
    const float* W_nt = (const float*)d_in[6];
    const float* b_nt = (const float*)d_in[7];
    const float* W_et = (const float*)d_in[8];
    const float* b_et = (const float*)d_in[9];
    const float* A0W  = (const float*)d_in[10];
    const float* A0b  = (const float*)d_in[11];
    const float* A1W  = (const float*)d_in[12];
    const float* A1b  = (const float*)d_in[13];
    const float* A2W  = (const float*)d_in[14];
    const float* A2b  = (const float*)d_in[15];
    const float* attn = (const float*)d_in[16];
    const float* Nm0W = (const float*)d_in[17];
    const float* Nm0b = (const float*)d_in[18];
    const float* Nm1W = (const float*)d_in[19];
    const float* Nm1b = (const float*)d_in[20];
    const float* Nm2W = (const float*)d_in[21];
    const float* Nm2b = (const float*)d_in[22];
    const float* Em0W = (const float*)d_in[23];
    const float* Em0b = (const float*)d_in[24];
    const float* Em1W = (const float*)d_in[25];
    const float* Em1b = (const float*)d_in[26];
    const float* Em2W = (const float*)d_in[27];
    const float* Em2b = (const float*)d_in[28];
    const float* linW = (const float*)d_in[29];
    const float* gcnW = (const float*)d_in[30];
    const float* gcnb = (const float*)d_in[31];

    float *Pni, *U, *V, *nodet, *bufA, *bufB, *em, *em2, *sc, *smax, *den, *agg;
    float *n0, *n1, *deg, *Wc1, *Wc2, *Wc3;
    cudaGetSymbolAddress((void**)&Pni,  g_Pni);
    cudaGetSymbolAddress((void**)&U,    g_U);
    cudaGetSymbolAddress((void**)&V,    g_V);
    cudaGetSymbolAddress((void**)&nodet,g_nodet);
    cudaGetSymbolAddress((void**)&bufA, g_bufA);
    cudaGetSymbolAddress((void**)&bufB, g_bufB);
    cudaGetSymbolAddress((void**)&em,   g_em);
    cudaGetSymbolAddress((void**)&em2,  g_em2);
    cudaGetSymbolAddress((void**)&sc,   g_sc);
    cudaGetSymbolAddress((void**)&smax, g_smax);
    cudaGetSymbolAddress((void**)&den,  g_den);
    cudaGetSymbolAddress((void**)&agg,  g_agg);
    cudaGetSymbolAddress((void**)&n0,   g_n0);
    cudaGetSymbolAddress((void**)&n1,   g_n1);
    cudaGetSymbolAddress((void**)&deg,  g_deg);
    cudaGetSymbolAddress((void**)&Wc1,  g_Wc1);
    cudaGetSymbolAddress((void**)&Wc2,  g_Wc2);
    cudaGetSymbolAddress((void**)&Wc3,  g_Wc3);

    float* out_node = (float*)d_out;               // [N,64]
    float* out_edge = out_node + NN * CC;          // [E,64]
    float* out_attn = out_edge + (size_t)EE * CC;  // [E]

    // big-tile GEMM (Ncol % 128 == 0)
    auto g128 = [&](const float* A, const float* B, const float* bias, float* C,
                    int M, int Ncol, int K, bool relu) {
        dim3 grid(Ncol / 128, ceildiv(M, 128));
        if (bias) {
            if (relu) gemm128<true,  true,  false, false><<<grid, 256>>>(A, B, bias, C, M, Ncol, K, nullptr, nullptr, nullptr, nullptr, nullptr);
            else      gemm128<false, true,  false, false><<<grid, 256>>>(A, B, bias, C, M, Ncol, K, nullptr, nullptr, nullptr, nullptr, nullptr);
        } else {
            if (relu) gemm128<true,  false, false, false><<<grid, 256>>>(A, B, bias, C, M, Ncol, K, nullptr, nullptr, nullptr, nullptr, nullptr);
            else      gemm128<false, false, false, false><<<grid, 256>>>(A, B, bias, C, M, Ncol, K, nullptr, nullptr, nullptr, nullptr, nullptr);
        }
    };
    // Ncol == 64 GEMM
    auto g64 = [&](const float* A, const float* B, const float* bias, float* C,
                   int M, int K, bool relu, const float* Cadd) {
        int grid = ceildiv(M, 128);
        if (Cadd) {
            gemmN64<true, true, true><<<grid, 128>>>(A, B, bias, C, M, K, Cadd);
        } else if (bias) {
            if (relu) gemmN64<true,  true,  false><<<grid, 128>>>(A, B, bias, C, M, K, nullptr);
            else      gemmN64<false, true,  false><<<grid, 128>>>(A, B, bias, C, M, K, nullptr);
        } else {
            gemmN64<false, false, false><<<grid, 128>>>(A, B, bias, C, M, K, nullptr);
        }
    };

    // 0) init accumulators
    k_init<<<ceildiv(NN * HCC, 256), 256>>>(smax, den, agg, deg);

    // 1) weight pre-combination (tiny GEMMs)
    g128(W_nj,  A0W,             nullptr, Wc1, HCC, HCC, HCC, false);
    g128(W_ni,  A0W + 512 * HCC, nullptr, Wc2, HCC, HCC, HCC, false);
    g128(W_eij, A0W + 256 * HCC, nullptr, Wc3, INE, HCC, HCC, false);

    // 2) node-level projections
    g128(node, W_ni, nullptr, Pni, NN, HCC, INN, false);
    g128(node, Wc1,  nullptr, U,   NN, HCC, INN, false);
    g128(node, Wc2,  nullptr, V,   NN, HCC, INN, false);
    g64 (node, W_nt, b_nt, nodet,  NN, INN, false, nullptr);

    // 3) edge projections; f0 fused: relu(EP + A0b + U[dst] + V[src]) -> bufA
    {
        dim3 grid(HCC / 128, EE / 128);
        gemm128<true, true, true, false><<<grid, 256>>>(
            ef, Wc3, A0b, bufA, EE, HCC, INE, src, dst, U, V, nullptr);
    }
    g64(ef, W_et, b_et, out_edge, EE, INE, false, nullptr);   // edge_t -> out_edge

    // 4) edge MLP chain
    g128(bufA, A1W, A1b, bufB, EE, HCC, HCC, true);           // f1
    g128(bufB, A2W, A2b, bufA, EE, HCC, HCC, true);           // f2 == f

    // 5) attention softmax over dst segments
    k_scores<<<ceildiv(EE * 32, 256), 256>>>(bufA, attn, dst, sc, smax);
    k_expsum<<<ceildiv(EE * HH, 256), 256>>>(dst, smax, sc, den);
    k_alpha <<<ceildiv(EE * 64, 256), 256>>>(src, dst, sc, den, linW, Pni, agg, out_attn);

    // 6) edge output MLP: out_edge += mlp3(f)  (add fused into last layer)
    g64(bufA, Em0W, Em0b, em,  EE, HCC, true, nullptr);
    g64(em,   Em1W, Em1b, em2, EE, CC,  true, nullptr);
    g64(em2,  Em2W, Em2b, out_edge, EE, CC, true, out_edge);

    // 7) node output MLP + residual (fused), then GCN transform
    g64(agg, Nm0W, Nm0b, n0, NN, HCC, true, nullptr);
    g64(n0,  Nm1W, Nm1b, n1, NN, CC,  true, nullptr);
    g64(n1,  Nm2W, Nm2b, n0, NN, CC,  true, nodet);           // node_out = relu(...) + nodet
    g64(n0, gcnW, nullptr, n1, NN, CC, false, nullptr);       // xg

    // 8) GCN normalize + aggregate
    k_deg<<<ceildiv(EE, 256), 256>>>(src, dst, deg);
    k_dinv<<<ceildiv(NN, 256), 256>>>(deg);
    k_gcn_self<<<ceildiv(NN * CC, 256), 256>>>(deg, n1, gcnb, out_node);
    k_gcn_scatter<<<ceildiv(EE * 64, 256), 256>>>(src, dst, deg, n1, out_node);
}

// round 12
// speedup vs baseline: 2.3666x; 1.8771x over previous
#include <cuda_runtime.h>
#include <math.h>
#include <float.h>

#define NN   10000
#define EE   160000
#define INN  256
#define INE  128
#define CC   64
#define HH   4
#define HCC  256
#define UVSTR 768

// ---------------- scratch (device globals; no allocation allowed) ----------------
__device__ __align__(16) float g_Wcat[256 * 768];          // [K=256][Pni|U|V]
__device__ __align__(16) float g_PUV[(size_t)NN * 768];    // node @ Wcat
__device__ __align__(16) float g_Wc3[INE * HCC];
__device__ __align__(16) float g_nodet[NN * CC];
__device__ __align__(16) float g_bufA[(size_t)EE * HCC];
__device__ __align__(16) float g_bufB[(size_t)EE * HCC];
__device__ __align__(16) float g_em[EE * CC];
__device__ __align__(16) float g_em2[EE * CC];
__device__ __align__(16) float g_sc[EE * HH];
__device__ __align__(16) float g_smax[NN * HH];
__device__ __align__(16) float g_den[NN * HH];
__device__ __align__(16) float g_agg[NN * HCC];
__device__ __align__(16) float g_n0[NN * CC];
__device__ __align__(16) float g_n1[NN * CC];
__device__ __align__(16) float g_deg[NN];

// ---------------- helpers ----------------
__device__ __forceinline__ void atomicMaxF(float* addr, float val) {
    if (val >= 0.f) atomicMax((int*)addr, __float_as_int(val));
    else            atomicMin((unsigned int*)addr, __float_as_uint(val));
}

__device__ __forceinline__ unsigned f2tf(float x) {
    unsigned u;
    asm("cvt.rna.tf32.f32 %0, %1;" : "=r"(u) : "f"(x));
    return u;
}

__device__ __forceinline__ void mma_tf32(float* c, const unsigned* a, const unsigned* b) {
    asm volatile(
        "mma.sync.aligned.m16n8k8.row.col.f32.tf32.tf32.f32 "
        "{%0,%1,%2,%3}, {%4,%5,%6,%7}, {%8,%9}, {%0,%1,%2,%3};"
        : "+f"(c[0]), "+f"(c[1]), "+f"(c[2]), "+f"(c[3])
        : "r"(a[0]), "r"(a[1]), "r"(a[2]), "r"(a[3]), "r"(b[0]), "r"(b[1]));
}

static inline int ceildiv(int a, int b) { return (a + b - 1) / b; }

// =====================================================================
// TF32 tensor-core GEMM. BM=128, BK=16, BN in {64,128}. 256 threads.
// BN=128: 8 warps as 2x4, warp tile 64x32 (MT=4,NT=4)
// BN=64 : 8 warps as 4x2, warp tile 32x32 (MT=2,NT=4)
// C[M,Ncol] = A[M,K] @ B[K,Ncol]; K % 16 == 0, Ncol % BN == 0.
// Epilogue: bias, COMBINE(+U[dst]+V[src] with row stride 768), relu, +Cadd.
// =====================================================================
template <int BN, bool RELU, bool HASBIAS, bool COMBINE, bool ADDC>
__global__ __launch_bounds__(256)
void mma_gemm(const float* __restrict__ A, const float* __restrict__ B,
              const float* __restrict__ bias, float* __restrict__ C,
              int M, int Ncol, int K,
              const int* __restrict__ srcI, const int* __restrict__ dstI,
              const float* __restrict__ Uv, const float* __restrict__ Vv,
              const float* __restrict__ Cadd)
{
    constexpr int WM = (BN == 128) ? 64 : 32;
    constexpr int WN = 32;
    constexpr int MT = WM / 16;          // 4 or 2
    constexpr int NT = WN / 8;           // 4
    constexpr int SBS = BN + 8;          // sB k-row stride (bank = 8k+n, conflict-free)

    __shared__ unsigned sA[2][128][20];
    __shared__ unsigned sB[2][16][SBS];

    const int tid = threadIdx.x;
    const int wid = tid >> 5, lane = tid & 31;
    const int warp_m = (BN == 128) ? (wid >> 2) : (wid >> 1);
    const int warp_n = (BN == 128) ? (wid & 3) : (wid & 1);
    const int row0 = blockIdx.y * 128;
    const int col0 = blockIdx.x * BN;
    const int g = lane >> 2, tg = lane & 3;

    float acc[MT][NT][4];
#pragma unroll
    for (int i = 0; i < MT; i++)
#pragma unroll
        for (int j = 0; j < NT; j++)
#pragma unroll
            for (int q = 0; q < 4; q++) acc[i][j][q] = 0.f;

    const int nk = K >> 4;

    auto load_tile = [&](int t, int st) {
        const int k0 = t << 4;
        // A: 128 rows x 16 k = 2048 floats, 2 float4 per thread
#pragma unroll
        for (int i = 0; i < 2; i++) {
            int u = tid + i * 256;
            int r = u >> 2, kq = (u & 3) << 2;
            float4 v = make_float4(0.f, 0.f, 0.f, 0.f);
            if (row0 + r < M)
                v = *reinterpret_cast<const float4*>(A + (size_t)(row0 + r) * K + k0 + kq);
            uint4 w = make_uint4(f2tf(v.x), f2tf(v.y), f2tf(v.z), f2tf(v.w));
            *reinterpret_cast<uint4*>(&sA[st][r][kq]) = w;
        }
        // B: 16 k-rows x BN cols
        if (BN == 128) {
#pragma unroll
            for (int i = 0; i < 2; i++) {
                int u = tid + i * 256;
                int kb = u >> 5, n4 = (u & 31) << 2;
                float4 v = *reinterpret_cast<const float4*>(B + (size_t)(k0 + kb) * Ncol + col0 + n4);
                uint4 w = make_uint4(f2tf(v.x), f2tf(v.y), f2tf(v.z), f2tf(v.w));
                *reinterpret_cast<uint4*>(&sB[st][kb][n4]) = w;
            }
        } else {
            int kb = tid >> 4, n4 = (tid & 15) << 2;
            float4 v = *reinterpret_cast<const float4*>(B + (size_t)(k0 + kb) * Ncol + col0 + n4);
            uint4 w = make_uint4(f2tf(v.x), f2tf(v.y), f2tf(v.z), f2tf(v.w));
            *reinterpret_cast<uint4*>(&sB[st][kb][n4]) = w;
        }
    };

    load_tile(0, 0);
    __syncthreads();

    for (int t = 0; t < nk; t++) {
        const int cur = t & 1;
        if (t + 1 < nk) load_tile(t + 1, cur ^ 1);
#pragma unroll
        for (int kk = 0; kk < 16; kk += 8) {
            unsigned a[MT][4], b[NT][2];
#pragma unroll
            for (int mt = 0; mt < MT; mt++) {
                int r0 = warp_m * WM + mt * 16 + g;
                a[mt][0] = sA[cur][r0][kk + tg];
                a[mt][1] = sA[cur][r0 + 8][kk + tg];
                a[mt][2] = sA[cur][r0][kk + tg + 4];
                a[mt][3] = sA[cur][r0 + 8][kk + tg + 4];
            }
#pragma unroll
            for (int nt = 0; nt < NT; nt++) {
                int n = warp_n * WN + nt * 8 + g;
                b[nt][0] = sB[cur][kk + tg][n];
                b[nt][1] = sB[cur][kk + tg + 4][n];
            }
#pragma unroll
            for (int mt = 0; mt < MT; mt++)
#pragma unroll
                for (int nt = 0; nt < NT; nt++)
                    mma_tf32(acc[mt][nt], a[mt], b[nt]);
        }
        __syncthreads();
    }

    // epilogue: each thread owns rows (g + h*8) per mt, col pairs (tg*2)
#pragma unroll
    for (int mt = 0; mt < MT; mt++) {
#pragma unroll
        for (int h = 0; h < 2; h++) {
            const int r = row0 + warp_m * WM + mt * 16 + g + h * 8;
            if (r >= M) continue;
            int s = 0, d = 0;
            if (COMBINE) { s = srcI[r]; d = dstI[r]; }
#pragma unroll
            for (int nt = 0; nt < NT; nt++) {
                const int c = col0 + warp_n * WN + nt * 8 + tg * 2;
                float2 v = make_float2(acc[mt][nt][2 * h], acc[mt][nt][2 * h + 1]);
                if (HASBIAS) { v.x += bias[c]; v.y += bias[c + 1]; }
                if (COMBINE) {
                    float2 uu = *reinterpret_cast<const float2*>(Uv + (size_t)d * UVSTR + c);
                    float2 vv = *reinterpret_cast<const float2*>(Vv + (size_t)s * UVSTR + c);
                    v.x += uu.x + vv.x; v.y += uu.y + vv.y;
                }
                if (RELU) { v.x = fmaxf(v.x, 0.f); v.y = fmaxf(v.y, 0.f); }
                if (ADDC) {
                    float2 ad = *reinterpret_cast<const float2*>(Cadd + (size_t)r * Ncol + c);
                    v.x += ad.x; v.y += ad.y;
                }
                *reinterpret_cast<float2*>(C + (size_t)r * Ncol + c) = v;
            }
        }
    }
}

// =====================================================================
// Batched tiny fp32 GEMMs for weight pre-combination (3 in one launch).
// z=0: Wcat[:,256:512] = W_nj @ A0W[0:256]      (M=256)
// z=1: Wcat[:,512:768] = W_ni @ A0W[512:768]    (M=256)
// z=2: Wc3             = W_eij @ A0W[256:512]   (M=128)
// All K=256, N=256, A row-stride 256.
// =====================================================================
__global__ void k_wc3(const float* __restrict__ Wnj, const float* __restrict__ Wni,
                      const float* __restrict__ Weij, const float* __restrict__ A0W,
                      float* __restrict__ Wcat, float* __restrict__ Wc3)
{
    const float* A; const float* B; float* C; int M, ldC;
    if (blockIdx.z == 0)      { A = Wnj;  B = A0W;             C = Wcat + 256; M = 256; ldC = 768; }
    else if (blockIdx.z == 1) { A = Wni;  B = A0W + 512 * 256; C = Wcat + 512; M = 256; ldC = 768; }
    else                      { A = Weij; B = A0W + 256 * 256; C = Wc3;        M = 128; ldC = 256; }

    const int row0 = blockIdx.y * 64;
    if (row0 >= M) return;
    const int col0 = blockIdx.x * 64;

    __shared__ float sA[16][68];
    __shared__ float sB[16][68];
    const int tid = threadIdx.x;
    const int tx = tid & 15, ty = tid >> 4;
    const int lm = tid >> 2, lk = (tid & 3) * 4;
    const int lkb = tid >> 4, lcb = (tid & 15) * 4;

    float acc[4][4];
#pragma unroll
    for (int i = 0; i < 4; i++)
#pragma unroll
        for (int j = 0; j < 4; j++) acc[i][j] = 0.f;

    for (int k0 = 0; k0 < 256; k0 += 16) {
        float4 av = *reinterpret_cast<const float4*>(A + (size_t)(row0 + lm) * 256 + k0 + lk);
        sA[lk + 0][lm] = av.x; sA[lk + 1][lm] = av.y;
        sA[lk + 2][lm] = av.z; sA[lk + 3][lm] = av.w;
        float4 bv = *reinterpret_cast<const float4*>(B + (size_t)(k0 + lkb) * 256 + col0 + lcb);
        sB[lkb][lcb + 0] = bv.x; sB[lkb][lcb + 1] = bv.y;
        sB[lkb][lcb + 2] = bv.z; sB[lkb][lcb + 3] = bv.w;
        __syncthreads();
#pragma unroll
        for (int k = 0; k < 16; k++) {
            float a[4], b[4];
#pragma unroll
            for (int i = 0; i < 4; i++) a[i] = sA[k][ty + 16 * i];
#pragma unroll
            for (int j = 0; j < 4; j++) b[j] = sB[k][tx + 16 * j];
#pragma unroll
            for (int i = 0; i < 4; i++)
#pragma unroll
                for (int j = 0; j < 4; j++) acc[i][j] = fmaf(a[i], b[j], acc[i][j]);
        }
        __syncthreads();
    }
#pragma unroll
    for (int i = 0; i < 4; i++)
#pragma unroll
        for (int j = 0; j < 4; j++)
            C[(size_t)(row0 + ty + 16 * i) * ldC + col0 + tx + 16 * j] = acc[i][j];
}

__global__ void k_copyWni(const float* __restrict__ Wni, float* __restrict__ Wcat)
{
    int i = blockIdx.x * 256 + threadIdx.x;
    if (i < 256 * 256) Wcat[(size_t)(i >> 8) * 768 + (i & 255)] = Wni[i];
}

// ---------------- specialized kernels ----------------
__global__ void k_init(float* __restrict__ smax, float* __restrict__ den,
                       float* __restrict__ agg, float* __restrict__ deg)
{
    int i = blockIdx.x * 256 + threadIdx.x;
    if (i < NN * HCC) agg[i] = 0.f;
    if (i < NN * HH) { smax[i] = -FLT_MAX; den[i] = 0.f; }
    if (i < NN) deg[i] = 1.f;
}

__global__ void k_scores(const float* __restrict__ f, const float* __restrict__ attn,
                         const int* __restrict__ dst, float* __restrict__ sc,
                         float* __restrict__ smax)
{
    int warp = (blockIdx.x * blockDim.x + threadIdx.x) >> 5;
    int lane = threadIdx.x & 31;
    if (warp >= EE) return;
    const float* fr = f + (size_t)warp * HCC;
    int c0 = lane * 8;
    float p = 0.f;
#pragma unroll
    for (int i = 0; i < 8; i++) p = fmaf(fr[c0 + i], attn[c0 + i], p);
    p += __shfl_down_sync(0xffffffffu, p, 4, 8);
    p += __shfl_down_sync(0xffffffffu, p, 2, 8);
    p += __shfl_down_sync(0xffffffffu, p, 1, 8);
    if ((lane & 7) == 0) {
        int h = lane >> 3;
        sc[warp * 4 + h] = p;
        atomicMaxF(&smax[dst[warp] * 4 + h], p);
    }
}

__global__ void k_expsum(const int* __restrict__ dst, const float* __restrict__ smax,
                         float* __restrict__ sc, float* __restrict__ den)
{
    int idx = blockIdx.x * 256 + threadIdx.x;
    if (idx >= EE * HH) return;
    int e = idx >> 2, h = idx & 3;
    int d = dst[e];
    float ex = expf(sc[idx] - smax[d * 4 + h]);
    sc[idx] = ex;
    atomicAdd(&den[d * 4 + h], ex);
}

// Pni rows live in PUV with stride 768 (cols 0..255)
__global__ void k_alpha(const int* __restrict__ src, const int* __restrict__ dst,
                        const float* __restrict__ sc, const float* __restrict__ den,
                        const float* __restrict__ lin, const float* __restrict__ Pni,
                        float* __restrict__ agg, float* __restrict__ attnw)
{
    int gid = blockIdx.x * 256 + threadIdx.x;
    int e = gid >> 6, t = gid & 63;
    if (e >= EE) return;
    int s = src[e], d = dst[e];
    int h = t >> 4;
    float alpha = sc[e * 4 + h] / den[d * 4 + h];
    if (t == 0) {
        float aw = 0.f;
#pragma unroll
        for (int hh = 0; hh < 4; hh++) aw = fmaf(sc[e * 4 + hh] / den[d * 4 + hh], lin[hh], aw);
        attnw[e] = aw;
    }
    float4 pv = reinterpret_cast<const float4*>(Pni + (size_t)s * UVSTR)[t];
    float* ag = agg + (size_t)d * HCC + t * 4;
    atomicAdd(ag + 0, pv.x * alpha);
    atomicAdd(ag + 1, pv.y * alpha);
    atomicAdd(ag + 2, pv.z * alpha);
    atomicAdd(ag + 3, pv.w * alpha);
}

__global__ void k_deg(const int* __restrict__ src, const int* __restrict__ dst,
                      float* __restrict__ deg)
{
    int e = blockIdx.x * 256 + threadIdx.x;
    if (e >= EE) return;
    int s = src[e];
    if (s != dst[e]) atomicAdd(&deg[s], 1.f);
}

__global__ void k_dinv(float* __restrict__ deg)
{
    int i = blockIdx.x * 256 + threadIdx.x;
    if (i < NN) deg[i] = rsqrtf(deg[i]);
}

__global__ void k_gcn_self(const float* __restrict__ dinv, const float* __restrict__ xg,
                           const float* __restrict__ gb, float* __restrict__ outn)
{
    int idx = blockIdx.x * 256 + threadIdx.x;
    if (idx >= NN * CC) return;
    int n = idx >> 6, c = idx & 63;
    outn[idx] = dinv[n] * dinv[n] * xg[idx] + gb[c];
}

__global__ void k_gcn_scatter(const int* __restrict__ src, const int* __restrict__ dst,
                              const float* __restrict__ dinv, const float* __restrict__ xg,
                              float* __restrict__ outn)
{
    int gid = blockIdx.x * 256 + threadIdx.x;
    int e = gid >> 6, t = gid & 63;
    if (e >= EE) return;
    int s = src[e], d = dst[e];
    if (s == d) return;
    float coef = dinv[s] * dinv[d];
    atomicAdd(&outn[(size_t)d * CC + t], coef * xg[(size_t)s * CC + t]);
}

// ---------------- launch ----------------
extern "C" void kernel_launch(void* const* d_in, const int* in_sizes, int n_in,
                              void* d_out, int out_size)
{
    const float* node = (const float*)d_in[0];
    const float* ef   = (const float*)d_in[1];
    const int*   ei   = (const int*)d_in[2];
    const int* src = ei;
    const int* dst = ei + EE;
    const float* W_ni = (const float*)d_in[3];
    const float* W_nj = (const float*)d_in[4];
    const float* W_eij= (const float*)d_in[5];
    const float* W_nt = (const float*)d_in[6];
    const float* b_nt = (const float*)d_in[7];
    const float* W_et = (const float*)d_in[8];
    const float* b_et = (const float*)d_in[9];
    const float* A0W  = (const float*)d_in[10];
    const float* A0b  = (const float*)d_in[11];
    const float* A1W  = (const float*)d_in[12];
    const float* A1b  = (const float*)d_in[13];
    const float* A2W  = (const float*)d_in[14];
    const float* A2b  = (const float*)d_in[15];
    const float* attn = (const float*)d_in[16];
    const float* Nm0W = (const float*)d_in[17];
    const float* Nm0b = (const float*)d_in[18];
    const float* Nm1W = (const float*)d_in[19];
    const float* Nm1b = (const float*)d_in[20];
    const float* Nm2W = (const float*)d_in[21];
    const float* Nm2b = (const float*)d_in[22];
    const float* Em0W = (const float*)d_in[23];
    const float* Em0b = (const float*)d_in[24];
    const float* Em1W = (const float*)d_in[25];
    const float* Em1b = (const float*)d_in[26];
    const float* Em2W = (const float*)d_in[27];
    const float* Em2b = (const float*)d_in[28];
    const float* linW = (const float*)d_in[29];
    const float* gcnW = (const float*)d_in[30];
    const float* gcnb = (const float*)d_in[31];

    float *Wcat, *PUV, *Wc3, *nodet, *bufA, *bufB, *em, *em2, *sc, *smax, *den, *agg;
    float *n0, *n1, *deg;
    cudaGetSymbolAddress((void**)&Wcat, g_Wcat);
    cudaGetSymbolAddress((void**)&PUV,  g_PUV);
    cudaGetSymbolAddress((void**)&Wc3,  g_Wc3);
    cudaGetSymbolAddress((void**)&nodet,g_nodet);
    cudaGetSymbolAddress((void**)&bufA, g_bufA);
    cudaGetSymbolAddress((void**)&bufB, g_bufB);
    cudaGetSymbolAddress((void**)&em,   g_em);
    cudaGetSymbolAddress((void**)&em2,  g_em2);
    cudaGetSymbolAddress((void**)&sc,   g_sc);
    cudaGetSymbolAddress((void**)&smax, g_smax);
    cudaGetSymbolAddress((void**)&den,  g_den);
    cudaGetSymbolAddress((void**)&agg,  g_agg);
    cudaGetSymbolAddress((void**)&n0,   g_n0);
    cudaGetSymbolAddress((void**)&n1,   g_n1);
    cudaGetSymbolAddress((void**)&deg,  g_deg);

    float* out_node = (float*)d_out;               // [N,64]
    float* out_edge = out_node + NN * CC;          // [E,64]
    float* out_attn = out_edge + (size_t)EE * CC;  // [E]

    const float* Uv = PUV + 256;   // U region (dst), row stride 768
    const float* Vv = PUV + 512;   // V region (src)

    // 0) init accumulators + weight pre-combination
    k_init<<<ceildiv(NN * HCC, 256), 256>>>(smax, den, agg, deg);
    k_copyWni<<<256, 256>>>(W_ni, Wcat);
    k_wc3<<<dim3(4, 4, 3), 256>>>(W_nj, W_ni, W_eij, A0W, Wcat, Wc3);

    // 1) node-level projections: PUV = node @ Wcat  ([10000,768])
    mma_gemm<128, false, false, false, false><<<dim3(6, ceildiv(NN, 128)), 256>>>(
        node, Wcat, nullptr, PUV, NN, 768, 256, nullptr, nullptr, nullptr, nullptr, nullptr);
    mma_gemm<64, false, true, false, false><<<dim3(1, ceildiv(NN, 128)), 256>>>(
        node, W_nt, b_nt, nodet, NN, CC, 256, nullptr, nullptr, nullptr, nullptr, nullptr);

    // 2) edge projections; f0 fused: relu(ef@Wc3 + A0b + U[dst] + V[src]) -> bufA
    mma_gemm<128, true, true, true, false><<<dim3(2, EE / 128), 256>>>(
        ef, Wc3, A0b, bufA, EE, HCC, INE, src, dst, Uv, Vv, nullptr);
    mma_gemm<64, false, true, false, false><<<dim3(1, EE / 128), 256>>>(
        ef, W_et, b_et, out_edge, EE, CC, INE, nullptr, nullptr, nullptr, nullptr, nullptr);

    // 3) edge MLP chain (the big GEMMs)
    mma_gemm<128, true, true, false, false><<<dim3(2, EE / 128), 256>>>(
        bufA, A1W, A1b, bufB, EE, HCC, HCC, nullptr, nullptr, nullptr, nullptr, nullptr);
    mma_gemm<128, true, true, false, false><<<dim3(2, EE / 128), 256>>>(
        bufB, A2W, A2b, bufA, EE, HCC, HCC, nullptr, nullptr, nullptr, nullptr, nullptr);

    // 4) attention softmax over dst segments
    k_scores<<<ceildiv(EE * 32, 256), 256>>>(bufA, attn, dst, sc, smax);
    k_expsum<<<ceildiv(EE * HH, 256), 256>>>(dst, smax, sc, den);
    k_alpha <<<ceildiv(EE * 64, 256), 256>>>(src, dst, sc, den, linW, PUV, agg, out_attn);

    // 5) edge output MLP: out_edge += relu-mlp3(f)
    mma_gemm<64, true, true, false, false><<<dim3(1, EE / 128), 256>>>(
        bufA, Em0W, Em0b, em, EE, CC, HCC, nullptr, nullptr, nullptr, nullptr, nullptr);
    mma_gemm<64, true, true, false, false><<<dim3(1, EE / 128), 256>>>(
        em, Em1W, Em1b, em2, EE, CC, CC, nullptr, nullptr, nullptr, nullptr, nullptr);
    mma_gemm<64, true, true, false, true><<<dim3(1, EE / 128), 256>>>(
        em2, Em2W, Em2b, out_edge, EE, CC, CC, nullptr, nullptr, nullptr, nullptr, out_edge);

    // 6) node output MLP + residual (fused), then GCN transform
    mma_gemm<64, true, true, false, false><<<dim3(1, ceildiv(NN, 128)), 256>>>(
        agg, Nm0W, Nm0b, n0, NN, CC, HCC, nullptr, nullptr, nullptr, nullptr, nullptr);
    mma_gemm<64, true, true, false, false><<<dim3(1, ceildiv(NN, 128)), 256>>>(
        n0, Nm1W, Nm1b, n1, NN, CC, CC, nullptr, nullptr, nullptr, nullptr, nullptr);
    mma_gemm<64, true, true, false, true><<<dim3(1, ceildiv(NN, 128)), 256>>>(
        n1, Nm2W, Nm2b, n0, NN, CC, CC, nullptr, nullptr, nullptr, nullptr, nodet);
    mma_gemm<64, false, false, false, false><<<dim3(1, ceildiv(NN, 128)), 256>>>(
        n0, gcnW, nullptr, n1, NN, CC, CC, nullptr, nullptr, nullptr, nullptr, nullptr);

    // 7) GCN normalize + aggregate
    k_deg<<<ceildiv(EE, 256), 256>>>(src, dst, deg);
    k_dinv<<<ceildiv(NN, 256), 256>>>(deg);
    k_gcn_self<<<ceildiv(NN * CC, 256), 256>>>(deg, n1, gcnb, out_node);
    k_gcn_scatter<<<ceildiv(EE * 64, 256), 256>>>(src, dst, deg, n1, out_node);
}

// round 14
// speedup vs baseline: 2.5084x; 1.0599x over previous
#include <cuda_runtime.h>
#include <math.h>
#include <float.h>

#define NN   10000
#define EE   160000
#define INN  256
#define INE  128
#define CC   64
#define HH   4
#define HCC  256
#define UVSTR 768

// ---------------- scratch (device globals; no allocation allowed) ----------------
__device__ __align__(16) float g_Wcat[256 * 768];          // [K=256][Pni|U|V]
__device__ __align__(16) float g_PUV[(size_t)NN * 768];    // node @ Wcat
__device__ __align__(16) float g_Wc3[INE * HCC];
__device__ __align__(16) float g_nodet[NN * CC];
__device__ __align__(16) float g_bufA[(size_t)EE * HCC];
__device__ __align__(16) float g_bufB[(size_t)EE * HCC];
__device__ __align__(16) float g_em[EE * CC];
__device__ __align__(16) float g_em2[EE * CC];
__device__ __align__(16) float g_sc[EE * HH];
__device__ __align__(16) float g_smax[NN * HH];
__device__ __align__(16) float g_den[NN * HH];
__device__ __align__(16) float g_agg[NN * HCC];
__device__ __align__(16) float g_n0[NN * CC];
__device__ __align__(16) float g_n1[NN * CC];
__device__ __align__(16) float g_deg[NN];

// ---------------- helpers ----------------
__device__ __forceinline__ void atomicMaxF(float* addr, float val) {
    if (val >= 0.f) atomicMax((int*)addr, __float_as_int(val));
    else            atomicMin((unsigned int*)addr, __float_as_uint(val));
}

__device__ __forceinline__ unsigned f2tf(float x) {
    unsigned u;
    asm("cvt.rna.tf32.f32 %0, %1;" : "=r"(u) : "f"(x));
    return u;
}

__device__ __forceinline__ void mma_tf32(float* c, const unsigned* a, const unsigned* b) {
    asm volatile(
        "mma.sync.aligned.m16n8k8.row.col.f32.tf32.tf32.f32 "
        "{%0,%1,%2,%3}, {%4,%5,%6,%7}, {%8,%9}, {%0,%1,%2,%3};"
        : "+f"(c[0]), "+f"(c[1]), "+f"(c[2]), "+f"(c[3])
        : "r"(a[0]), "r"(a[1]), "r"(a[2]), "r"(a[3]), "r"(b[0]), "r"(b[1]));
}

static inline int ceildiv(int a, int b) { return (a + b - 1) / b; }

// =====================================================================
// TF32 tensor-core GEMM. BM=128, BK=16. Warp tile 32x32 (MT=2, NT=4).
// BN=128: 512 threads, 16 warps as 4x4.
// BN=64 : 256 threads,  8 warps as 4x2.
// C[M,Ncol] = A[M,K] @ B[K,Ncol]; K % 16 == 0, Ncol % BN == 0.
// Epilogue: bias, COMBINE(+U[dst]+V[src] stride 768), relu, +Cadd.
// =====================================================================
template <int BN, bool RELU, bool HASBIAS, bool COMBINE, bool ADDC>
__global__ __launch_bounds__((BN == 128) ? 512 : 256, (BN == 128) ? 2 : 4)
void mma_gemm(const float* __restrict__ A, const float* __restrict__ B,
              const float* __restrict__ bias, float* __restrict__ C,
              int M, int Ncol, int K,
              const int* __restrict__ srcI, const int* __restrict__ dstI,
              const float* __restrict__ Uv, const float* __restrict__ Vv,
              const float* __restrict__ Cadd)
{
    constexpr int MT = 2;
    constexpr int NT = 4;
    constexpr int SBS = BN + 8;

    __shared__ unsigned sA[2][128][20];
    __shared__ unsigned sB[2][16][SBS];

    const int tid = threadIdx.x;
    const int wid = tid >> 5, lane = tid & 31;
    const int warp_m = (BN == 128) ? (wid >> 2) : (wid >> 1);   // 0..3
    const int warp_n = (BN == 128) ? (wid & 3) : (wid & 1);
    const int row0 = blockIdx.y * 128;
    const int col0 = blockIdx.x * BN;
    const int g = lane >> 2, tg = lane & 3;

    float acc[MT][NT][4];
#pragma unroll
    for (int i = 0; i < MT; i++)
#pragma unroll
        for (int j = 0; j < NT; j++)
#pragma unroll
            for (int q = 0; q < 4; q++) acc[i][j][q] = 0.f;

    const int nk = K >> 4;

    auto load_tile = [&](int t, int st) {
        const int k0 = t << 4;
        if (BN == 128) {
            // 512 threads: one float4 each for A (128x16) and B (16x128)
            {
                int r = tid >> 2, kq = (tid & 3) << 2;
                float4 v = make_float4(0.f, 0.f, 0.f, 0.f);
                if (row0 + r < M)
                    v = *reinterpret_cast<const float4*>(A + (size_t)(row0 + r) * K + k0 + kq);
                uint4 w = make_uint4(f2tf(v.x), f2tf(v.y), f2tf(v.z), f2tf(v.w));
                *reinterpret_cast<uint4*>(&sA[st][r][kq]) = w;
            }
            {
                int kb = tid >> 5, n4 = (tid & 31) << 2;
                float4 v = *reinterpret_cast<const float4*>(B + (size_t)(k0 + kb) * Ncol + col0 + n4);
                uint4 w = make_uint4(f2tf(v.x), f2tf(v.y), f2tf(v.z), f2tf(v.w));
                *reinterpret_cast<uint4*>(&sB[st][kb][n4]) = w;
            }
        } else {
            // 256 threads: two float4 for A, one for B (16x64)
#pragma unroll
            for (int i = 0; i < 2; i++) {
                int u = tid + i * 256;
                int r = u >> 2, kq = (u & 3) << 2;
                float4 v = make_float4(0.f, 0.f, 0.f, 0.f);
                if (row0 + r < M)
                    v = *reinterpret_cast<const float4*>(A + (size_t)(row0 + r) * K + k0 + kq);
                uint4 w = make_uint4(f2tf(v.x), f2tf(v.y), f2tf(v.z), f2tf(v.w));
                *reinterpret_cast<uint4*>(&sA[st][r][kq]) = w;
            }
            {
                int kb = tid >> 4, n4 = (tid & 15) << 2;
                float4 v = *reinterpret_cast<const float4*>(B + (size_t)(k0 + kb) * Ncol + col0 + n4);
                uint4 w = make_uint4(f2tf(v.x), f2tf(v.y), f2tf(v.z), f2tf(v.w));
                *reinterpret_cast<uint4*>(&sB[st][kb][n4]) = w;
            }
        }
    };

    load_tile(0, 0);
    __syncthreads();

    for (int t = 0; t < nk; t++) {
        const int cur = t & 1;
        if (t + 1 < nk) load_tile(t + 1, cur ^ 1);
#pragma unroll
        for (int kk = 0; kk < 16; kk += 8) {
            unsigned a[MT][4], b[NT][2];
#pragma unroll
            for (int mt = 0; mt < MT; mt++) {
                int r0 = warp_m * 32 + mt * 16 + g;
                a[mt][0] = sA[cur][r0][kk + tg];
                a[mt][1] = sA[cur][r0 + 8][kk + tg];
                a[mt][2] = sA[cur][r0][kk + tg + 4];
                a[mt][3] = sA[cur][r0 + 8][kk + tg + 4];
            }
#pragma unroll
            for (int nt = 0; nt < NT; nt++) {
                int n = warp_n * 32 + nt * 8 + g;
                b[nt][0] = sB[cur][kk + tg][n];
                b[nt][1] = sB[cur][kk + tg + 4][n];
            }
#pragma unroll
            for (int mt = 0; mt < MT; mt++)
#pragma unroll
                for (int nt = 0; nt < NT; nt++)
                    mma_tf32(acc[mt][nt], a[mt], b[nt]);
        }
        __syncthreads();
    }

#pragma unroll
    for (int mt = 0; mt < MT; mt++) {
#pragma unroll
        for (int h = 0; h < 2; h++) {
            const int r = row0 + warp_m * 32 + mt * 16 + g + h * 8;
            if (r >= M) continue;
            int s = 0, d = 0;
            if (COMBINE) { s = srcI[r]; d = dstI[r]; }
#pragma unroll
            for (int nt = 0; nt < NT; nt++) {
                const int c = col0 + warp_n * 32 + nt * 8 + tg * 2;
                float2 v = make_float2(acc[mt][nt][2 * h], acc[mt][nt][2 * h + 1]);
                if (HASBIAS) { v.x += bias[c]; v.y += bias[c + 1]; }
                if (COMBINE) {
                    float2 uu = *reinterpret_cast<const float2*>(Uv + (size_t)d * UVSTR + c);
                    float2 vv = *reinterpret_cast<const float2*>(Vv + (size_t)s * UVSTR + c);
                    v.x += uu.x + vv.x; v.y += uu.y + vv.y;
                }
                if (RELU) { v.x = fmaxf(v.x, 0.f); v.y = fmaxf(v.y, 0.f); }
                if (ADDC) {
                    float2 ad = *reinterpret_cast<const float2*>(Cadd + (size_t)r * Ncol + c);
                    v.x += ad.x; v.y += ad.y;
                }
                *reinterpret_cast<float2*>(C + (size_t)r * Ncol + c) = v;
            }
        }
    }
}

// =====================================================================
// Batched tiny fp32 GEMMs for weight pre-combination (3 in one launch).
// =====================================================================
__global__ void k_wc3(const float* __restrict__ Wnj, const float* __restrict__ Wni,
                      const float* __restrict__ Weij, const float* __restrict__ A0W,
                      float* __restrict__ Wcat, float* __restrict__ Wc3)
{
    const float* A; const float* B; float* C; int M, ldC;
    if (blockIdx.z == 0)      { A = Wnj;  B = A0W;             C = Wcat + 256; M = 256; ldC = 768; }
    else if (blockIdx.z == 1) { A = Wni;  B = A0W + 512 * 256; C = Wcat + 512; M = 256; ldC = 768; }
    else                      { A = Weij; B = A0W + 256 * 256; C = Wc3;        M = 128; ldC = 256; }

    const int row0 = blockIdx.y * 64;
    if (row0 >= M) return;
    const int col0 = blockIdx.x * 64;

    __shared__ float sA[16][68];
    __shared__ float sB[16][68];
    const int tid = threadIdx.x;
    const int tx = tid & 15, ty = tid >> 4;
    const int lm = tid >> 2, lk = (tid & 3) * 4;
    const int lkb = tid >> 4, lcb = (tid & 15) * 4;

    float acc[4][4];
#pragma unroll
    for (int i = 0; i < 4; i++)
#pragma unroll
        for (int j = 0; j < 4; j++) acc[i][j] = 0.f;

    for (int k0 = 0; k0 < 256; k0 += 16) {
        float4 av = *reinterpret_cast<const float4*>(A + (size_t)(row0 + lm) * 256 + k0 + lk);
        sA[lk + 0][lm] = av.x; sA[lk + 1][lm] = av.y;
        sA[lk + 2][lm] = av.z; sA[lk + 3][lm] = av.w;
        float4 bv = *reinterpret_cast<const float4*>(B + (size_t)(k0 + lkb) * 256 + col0 + lcb);
        sB[lkb][lcb + 0] = bv.x; sB[lkb][lcb + 1] = bv.y;
        sB[lkb][lcb + 2] = bv.z; sB[lkb][lcb + 3] = bv.w;
        __syncthreads();
#pragma unroll
        for (int k = 0; k < 16; k++) {
            float a[4], b[4];
#pragma unroll
            for (int i = 0; i < 4; i++) a[i] = sA[k][ty + 16 * i];
#pragma unroll
            for (int j = 0; j < 4; j++) b[j] = sB[k][tx + 16 * j];
#pragma unroll
            for (int i = 0; i < 4; i++)
#pragma unroll
                for (int j = 0; j < 4; j++) acc[i][j] = fmaf(a[i], b[j], acc[i][j]);
        }
        __syncthreads();
    }
#pragma unroll
    for (int i = 0; i < 4; i++)
#pragma unroll
        for (int j = 0; j < 4; j++)
            C[(size_t)(row0 + ty + 16 * i) * ldC + col0 + tx + 16 * j] = acc[i][j];
}

__global__ void k_copyWni(const float* __restrict__ Wni, float* __restrict__ Wcat)
{
    int i = blockIdx.x * 256 + threadIdx.x;
    if (i < 256 * 256) Wcat[(size_t)(i >> 8) * 768 + (i & 255)] = Wni[i];
}

// ---------------- specialized kernels ----------------
__global__ void k_init(float* __restrict__ smax, float* __restrict__ den,
                       float* __restrict__ agg, float* __restrict__ deg)
{
    int i = blockIdx.x * 256 + threadIdx.x;
    if (i < NN * HCC) agg[i] = 0.f;
    if (i < NN * HH) { smax[i] = -FLT_MAX; den[i] = 0.f; }
    if (i < NN) deg[i] = 1.f;
}

__global__ void k_scores(const float* __restrict__ f, const float* __restrict__ attn,
                         const int* __restrict__ dst, float* __restrict__ sc,
                         float* __restrict__ smax)
{
    int warp = (blockIdx.x * blockDim.x + threadIdx.x) >> 5;
    int lane = threadIdx.x & 31;
    if (warp >= EE) return;
    const float* fr = f + (size_t)warp * HCC;
    int c0 = lane * 8;
    float p = 0.f;
#pragma unroll
    for (int i = 0; i < 8; i++) p = fmaf(fr[c0 + i], attn[c0 + i], p);
    p += __shfl_down_sync(0xffffffffu, p, 4, 8);
    p += __shfl_down_sync(0xffffffffu, p, 2, 8);
    p += __shfl_down_sync(0xffffffffu, p, 1, 8);
    if ((lane & 7) == 0) {
        int h = lane >> 3;
        sc[warp * 4 + h] = p;
        atomicMaxF(&smax[dst[warp] * 4 + h], p);
    }
}

__global__ void k_expsum(const int* __restrict__ dst, const float* __restrict__ smax,
                         float* __restrict__ sc, float* __restrict__ den)
{
    int idx = blockIdx.x * 256 + threadIdx.x;
    if (idx >= EE * HH) return;
    int e = idx >> 2, h = idx & 3;
    int d = dst[e];
    float ex = expf(sc[idx] - smax[d * 4 + h]);
    sc[idx] = ex;
    atomicAdd(&den[d * 4 + h], ex);
}

// Pni rows live in PUV with stride 768 (cols 0..255)
__global__ void k_alpha(const int* __restrict__ src, const int* __restrict__ dst,
                        const float* __restrict__ sc, const float* __restrict__ den,
                        const float* __restrict__ lin, const float* __restrict__ Pni,
                        float* __restrict__ agg, float* __restrict__ attnw)
{
    int gid = blockIdx.x * 256 + threadIdx.x;
    int e = gid >> 6, t = gid & 63;
    if (e >= EE) return;
    int s = src[e], d = dst[e];
    int h = t >> 4;
    float alpha = sc[e * 4 + h] / den[d * 4 + h];
    if (t == 0) {
        float aw = 0.f;
#pragma unroll
        for (int hh = 0; hh < 4; hh++) aw = fmaf(sc[e * 4 + hh] / den[d * 4 + hh], lin[hh], aw);
        attnw[e] = aw;
    }
    float4 pv = reinterpret_cast<const float4*>(Pni + (size_t)s * UVSTR)[t];
    float* ag = agg + (size_t)d * HCC + t * 4;
    atomicAdd(ag + 0, pv.x * alpha);
    atomicAdd(ag + 1, pv.y * alpha);
    atomicAdd(ag + 2, pv.z * alpha);
    atomicAdd(ag + 3, pv.w * alpha);
}

__global__ void k_deg(const int* __restrict__ src, const int* __restrict__ dst,
                      float* __restrict__ deg)
{
    int e = blockIdx.x * 256 + threadIdx.x;
    if (e >= EE) return;
    int s = src[e];
    if (s != dst[e]) atomicAdd(&deg[s], 1.f);
}

__global__ void k_dinv(float* __restrict__ deg)
{
    int i = blockIdx.x * 256 + threadIdx.x;
    if (i < NN) deg[i] = rsqrtf(deg[i]);
}

__global__ void k_gcn_self(const float* __restrict__ dinv, const float* __restrict__ xg,
                           const float* __restrict__ gb, float* __restrict__ outn)
{
    int idx = blockIdx.x * 256 + threadIdx.x;
    if (idx >= NN * CC) return;
    int n = idx >> 6, c = idx & 63;
    outn[idx] = dinv[n] * dinv[n] * xg[idx] + gb[c];
}

__global__ void k_gcn_scatter(const int* __restrict__ src, const int* __restrict__ dst,
                              const float* __restrict__ dinv, const float* __restrict__ xg,
                              float* __restrict__ outn)
{
    int gid = blockIdx.x * 256 + threadIdx.x;
    int e = gid >> 6, t = gid & 63;
    if (e >= EE) return;
    int s = src[e], d = dst[e];
    if (s == d) return;
    float coef = dinv[s] * dinv[d];
    atomicAdd(&outn[(size_t)d * CC + t], coef * xg[(size_t)s * CC + t]);
}

// ---------------- launch ----------------
extern "C" void kernel_launch(void* const* d_in, const int* in_sizes, int n_in,
                              void* d_out, int out_size)
{
    const float* node = (const float*)d_in[0];
    const float* ef   = (const float*)d_in[1];
    const int*   ei   = (const int*)d_in[2];
    const int* src = ei;
    const int* dst = ei + EE;
    const float* W_ni = (const float*)d_in[3];
    const float* W_nj = (const float*)d_in[4];
    const float* W_eij= (const float*)d_in[5];
    const float* W_nt = (const float*)d_in[6];
    const float* b_nt = (const float*)d_in[7];
    const float* W_et = (const float*)d_in[8];
    const float* b_et = (const float*)d_in[9];
    const float* A0W  = (const float*)d_in[10];
    const float* A0b  = (const float*)d_in[11];
    const float* A1W  = (const float*)d_in[12];
    const float* A1b  = (const float*)d_in[13];
    const float* A2W  = (const float*)d_in[14];
    const float* A2b  = (const float*)d_in[15];
    const float* attn = (const float*)d_in[16];
    const float* Nm0W = (const float*)d_in[17];
    const float* Nm0b = (const float*)d_in[18];
    const float* Nm1W = (const float*)d_in[19];
    const float* Nm1b = (const float*)d_in[20];
    const float* Nm2W = (const float*)d_in[21];
    const float* Nm2b = (const float*)d_in[22];
    const float* Em0W = (const float*)d_in[23];
    const float* Em0b = (const float*)d_in[24];
    const float* Em1W = (const float*)d_in[25];
    const float* Em1b = (const float*)d_in[26];
    const float* Em2W = (const float*)d_in[27];
    const float* Em2b = (const float*)d_in[28];
    const float* linW = (const float*)d_in[29];
    const float* gcnW = (const float*)d_in[30];
    const float* gcnb = (const float*)d_in[31];

    float *Wcat, *PUV, *Wc3, *nodet, *bufA, *bufB, *em, *em2, *sc, *smax, *den, *agg;
    float *n0, *n1, *deg;
    cudaGetSymbolAddress((void**)&Wcat, g_Wcat);
    cudaGetSymbolAddress((void**)&PUV,  g_PUV);
    cudaGetSymbolAddress((void**)&Wc3,  g_Wc3);
    cudaGetSymbolAddress((void**)&nodet,g_nodet);
    cudaGetSymbolAddress((void**)&bufA, g_bufA);
    cudaGetSymbolAddress((void**)&bufB, g_bufB);
    cudaGetSymbolAddress((void**)&em,   g_em);
    cudaGetSymbolAddress((void**)&em2,  g_em2);
    cudaGetSymbolAddress((void**)&sc,   g_sc);
    cudaGetSymbolAddress((void**)&smax, g_smax);
    cudaGetSymbolAddress((void**)&den,  g_den);
    cudaGetSymbolAddress((void**)&agg,  g_agg);
    cudaGetSymbolAddress((void**)&n0,   g_n0);
    cudaGetSymbolAddress((void**)&n1,   g_n1);
    cudaGetSymbolAddress((void**)&deg,  g_deg);

    float* out_node = (float*)d_out;               // [N,64]
    float* out_edge = out_node + NN * CC;          // [E,64]
    float* out_attn = out_edge + (size_t)EE * CC;  // [E]

    const float* Uv = PUV + 256;   // U region (dst), row stride 768
    const float* Vv = PUV + 512;   // V region (src)

    // 0) init accumulators + weight pre-combination
    k_init<<<ceildiv(NN * HCC, 256), 256>>>(smax, den, agg, deg);
    k_copyWni<<<256, 256>>>(W_ni, Wcat);
    k_wc3<<<dim3(4, 4, 3), 256>>>(W_nj, W_ni, W_eij, A0W, Wcat, Wc3);

    // 1) node-level projections: PUV = node @ Wcat  ([10000,768])
    mma_gemm<128, false, false, false, false><<<dim3(6, ceildiv(NN, 128)), 512>>>(
        node, Wcat, nullptr, PUV, NN, 768, 256, nullptr, nullptr, nullptr, nullptr, nullptr);
    mma_gemm<64, false, true, false, false><<<dim3(1, ceildiv(NN, 128)), 256>>>(
        node, W_nt, b_nt, nodet, NN, CC, 256, nullptr, nullptr, nullptr, nullptr, nullptr);

    // 2) edge projections; f0 fused: relu(ef@Wc3 + A0b + U[dst] + V[src]) -> bufA
    mma_gemm<128, true, true, true, false><<<dim3(2, EE / 128), 512>>>(
        ef, Wc3, A0b, bufA, EE, HCC, INE, src, dst, Uv, Vv, nullptr);
    mma_gemm<64, false, true, false, false><<<dim3(1, EE / 128), 256>>>(
        ef, W_et, b_et, out_edge, EE, CC, INE, nullptr, nullptr, nullptr, nullptr, nullptr);

    // 3) edge MLP chain (the big GEMMs)
    mma_gemm<128, true, true, false, false><<<dim3(2, EE / 128), 512>>>(
        bufA, A1W, A1b, bufB, EE, HCC, HCC, nullptr, nullptr, nullptr, nullptr, nullptr);
    mma_gemm<128, true, true, false, false><<<dim3(2, EE / 128), 512>>>(
        bufB, A2W, A2b, bufA, EE, HCC, HCC, nullptr, nullptr, nullptr, nullptr, nullptr);

    // 4) attention softmax over dst segments
    k_scores<<<ceildiv(EE * 32, 256), 256>>>(bufA, attn, dst, sc, smax);
    k_expsum<<<ceildiv(EE * HH, 256), 256>>>(dst, smax, sc, den);
    k_alpha <<<ceildiv(EE * 64, 256), 256>>>(src, dst, sc, den, linW, PUV, agg, out_attn);

    // 5) edge output MLP: out_edge += relu-mlp3(f)
    mma_gemm<64, true, true, false, false><<<dim3(1, EE / 128), 256>>>(
        bufA, Em0W, Em0b, em, EE, CC, HCC, nullptr, nullptr, nullptr, nullptr, nullptr);
    mma_gemm<64, true, true, false, false><<<dim3(1, EE / 128), 256>>>(
        em, Em1W, Em1b, em2, EE, CC, CC, nullptr, nullptr, nullptr, nullptr, nullptr);
    mma_gemm<64, true, true, false, true><<<dim3(1, EE / 128), 256>>>(
        em2, Em2W, Em2b, out_edge, EE, CC, CC, nullptr, nullptr, nullptr, nullptr, out_edge);

    // 6) node output MLP + residual (fused), then GCN transform
    mma_gemm<64, true, true, false, false><<<dim3(1, ceildiv(NN, 128)), 256>>>(
        agg, Nm0W, Nm0b, n0, NN, CC, HCC, nullptr, nullptr, nullptr, nullptr, nullptr);
    mma_gemm<64, true, true, false, false><<<dim3(1, ceildiv(NN, 128)), 256>>>(
        n0, Nm1W, Nm1b, n1, NN, CC, CC, nullptr, nullptr, nullptr, nullptr, nullptr);
    mma_gemm<64, true, true, false, true><<<dim3(1, ceildiv(NN, 128)), 256>>>(
        n1, Nm2W, Nm2b, n0, NN, CC, CC, nullptr, nullptr, nullptr, nullptr, nodet);
    mma_gemm<64, false, false, false, false><<<dim3(1, ceildiv(NN, 128)), 256>>>(
        n0, gcnW, nullptr, n1, NN, CC, CC, nullptr, nullptr, nullptr, nullptr, nullptr);

    // 7) GCN normalize + aggregate
    k_deg<<<ceildiv(EE, 256), 256>>>(src, dst, deg);
    k_dinv<<<ceildiv(NN, 256), 256>>>(deg);
    k_gcn_self<<<ceildiv(NN * CC, 256), 256>>>(deg, n1, gcnb, out_node);
    k_gcn_scatter<<<ceildiv(EE * 64, 256), 256>>>(src, dst, deg, n1, out_node);
}